// round 3
// baseline (speedup 1.0000x reference)
#include <cuda_runtime.h>
#include <cuda_bf16.h>

// Problem constants
#define B 4
#define P 12000
#define C 64
#define H 512
#define W 512
#define SLOT_CAP 80   // staged feature rows in smem; overflow falls back to gmem

// Winner pillar map per output pixel, encoded as (p+1); 0 = empty.
// Zero-initialized at module load; gather kernel restores its strip to 0
// (read-then-clear by the same thread), so the all-zeros invariant holds
// before every kernel_launch call / graph replay.
__device__ int g_winner[B * H * W];

// Kernel 1: one thread per (b, p). Reference semantics: sequential .at[].set
// means the LARGEST pillar index wins per pixel -> atomicMax on (p+1).
__global__ void scatter_winner_kernel(const int* __restrict__ coords) {
    int i = blockIdx.x * blockDim.x + threadIdx.x;   // i = b*P + p
    if (i >= B * P) return;
    int b = i / P;
    int p = i - b * P;
    int4 c4 = reinterpret_cast<const int4*>(coords)[i];  // (batch, y, x, z)
    int y = c4.y;
    int x = c4.z;
    if ((unsigned)x < (unsigned)W && (unsigned)y < (unsigned)H) {
        atomicMax(&g_winner[(b * H + y) * W + x], p + 1);
    }
}

// Kernel 2: one block per (b, y) output ROW (512 pixels, all 64 channels).
// 2048 blocks x 256 threads. 128 KB of streaming stores per block.
__global__ __launch_bounds__(256) void gather_out_kernel(
    const float* __restrict__ feat, float* __restrict__ out) {
    __shared__ int   s_slot[W];              // per-pixel slot id or -1
    __shared__ int   s_pid[W];               // slot -> pillar index (full range)
    __shared__ int   s_n;
    __shared__ float s_feat[SLOT_CAP * 65];  // padded rows -> conflict-free

    const int y   = blockIdx.x;
    const int b   = blockIdx.y;
    const int tid = threadIdx.x;

    // --- Phase 1: read winner row (int4), clear it (same thread => ordered),
    //              compact occupied pixels into slots.
    int4 w4 = make_int4(0, 0, 0, 0);
    int4* wrow4 = reinterpret_cast<int4*>(g_winner + (b * H + y) * W);
    if (tid < W / 4) w4 = wrow4[tid];
    if (tid == 0) s_n = 0;
    __syncthreads();

    if (tid < W / 4) {
        wrow4[tid] = make_int4(0, 0, 0, 0);
        const int wv[4] = {w4.x, w4.y, w4.z, w4.w};
        #pragma unroll
        for (int j = 0; j < 4; ++j) {
            int sl = -1;
            if (wv[j] > 0) {
                sl = atomicAdd(&s_n, 1);
                s_pid[sl] = wv[j] - 1;
            }
            s_slot[tid * 4 + j] = sl;
        }
    }
    __syncthreads();

    // --- Phase 2: stage occupied feature rows into smem (coalesced float4).
    const float* featb = feat + (size_t)b * P * C;
    const float4* featb4 = reinterpret_cast<const float4*>(featb);
    const int n_stage = min(s_n, SLOT_CAP);
    for (int i = tid; i < n_stage * (C / 4); i += 256) {
        int sl = i >> 4;          // C/4 == 16
        int q  = i & 15;
        float4 v = __ldg(&featb4[(size_t)s_pid[sl] * (C / 4) + q]);
        float* dst = &s_feat[sl * 65 + q * 4];
        dst[0] = v.x; dst[1] = v.y; dst[2] = v.z; dst[3] = v.w;
    }
    __syncthreads();

    // --- Phase 3: emit. Thread owns 4 fixed pixels (xq), loops 32 channels.
    // c = (tid>>7) + 2*it  covers 0..63; each warp stores 512B contiguous.
    const int xq = tid & 127;
    const int c0 = tid >> 7;

    int s0 = s_slot[xq * 4 + 0];
    int s1 = s_slot[xq * 4 + 1];
    int s2 = s_slot[xq * 4 + 2];
    int s3 = s_slot[xq * 4 + 3];
    // Overflow pillar ids (slot >= SLOT_CAP) — statistically never taken.
    const int p0 = (s0 >= SLOT_CAP) ? s_pid[s0] : 0;
    const int p1 = (s1 >= SLOT_CAP) ? s_pid[s1] : 0;
    const int p2 = (s2 >= SLOT_CAP) ? s_pid[s2] : 0;
    const int p3 = (s3 >= SLOT_CAP) ? s_pid[s3] : 0;

    float4* out4 = reinterpret_cast<float4*>(out);
    // float4 index of out[b][c0][y][0] + xq
    size_t addr = ((size_t)(b * C + c0) * H + y) * (W / 4) + xq;
    const size_t addr_step = (size_t)2 * H * (W / 4);   // c += 2

    #pragma unroll 4
    for (int it = 0; it < 32; ++it) {
        const int c = c0 + 2 * it;
        float4 v;
        v.x = (s0 < 0) ? 0.0f : (s0 < SLOT_CAP ? s_feat[s0 * 65 + c]
                                               : featb[(size_t)p0 * C + c]);
        v.y = (s1 < 0) ? 0.0f : (s1 < SLOT_CAP ? s_feat[s1 * 65 + c]
                                               : featb[(size_t)p1 * C + c]);
        v.z = (s2 < 0) ? 0.0f : (s2 < SLOT_CAP ? s_feat[s2 * 65 + c]
                                               : featb[(size_t)p2 * C + c]);
        v.w = (s3 < 0) ? 0.0f : (s3 < SLOT_CAP ? s_feat[s3 * 65 + c]
                                               : featb[(size_t)p3 * C + c]);
        __stcs(&out4[addr], v);
        addr += addr_step;
    }
}

extern "C" void kernel_launch(void* const* d_in, const int* in_sizes, int n_in,
                              void* d_out, int out_size) {
    const float* feat   = (const float*)d_in[0];   // [B, P, C] fp32
    const int*   coords = (const int*)d_in[1];     // [B, P, 4] int32
    float* out = (float*)d_out;                    // [B, C, H, W] fp32

    scatter_winner_kernel<<<(B * P + 255) / 256, 256>>>(coords);

    dim3 grid(H, B);   // 2048 blocks, one per output row
    gather_out_kernel<<<grid, 256>>>(feat, out);
}